// round 14
// baseline (speedup 1.0000x reference)
#include <cuda_runtime.h>
#include <cuda_fp16.h>
#include <cstdint>

// ---------------------------------------------------------------------------
// Problem constants
// ---------------------------------------------------------------------------
#define T_TOKENS 4096
#define DDIM 1024
#define FDIM 4096
#define NEXP 8
#define BM 128
#define BK 64
#define MAX_MT 72
#define ROWS_CAP (MAX_MT * 128)

// ---------------------------------------------------------------------------
// Device scratch (fp16 operands, fp32 outputs)
// ---------------------------------------------------------------------------
__device__ int    g_cnt[NEXP];
__device__ int    g_cur[NEXP];
__device__ int    g_done;
__device__ int    g_nmt;
__device__ int    g_tile_e[MAX_MT];
__device__ int    g_tile_r[MAX_MT];
__device__ int    g_row_token[ROWS_CAP];
__device__ int    g_tok_e[T_TOKENS * 2];
__device__ int    g_tok_row[T_TOKENS * 2];
__device__ float  g_tok_w[T_TOKENS * 2];
__device__ __half g_H[(size_t)ROWS_CAP * FDIM];
__device__ float  g_Y1[(size_t)ROWS_CAP * DDIM];
__device__ float  g_Y2[(size_t)ROWS_CAP * DDIM];
__device__ __half g_xt[(size_t)T_TOKENS * DDIM];
__device__ __half g_w1t[(size_t)NEXP * DDIM * FDIM];
__device__ __half g_w3t[(size_t)NEXP * DDIM * FDIM];
__device__ __half g_w2t[(size_t)NEXP * DDIM * FDIM];

// ---------------------------------------------------------------------------
// Helpers
// ---------------------------------------------------------------------------
__device__ __forceinline__ uint32_t smem_u32(const void* p) {
    uint32_t a;
    asm("{ .reg .u64 t; cvta.to.shared.u64 t, %1; cvt.u32.u64 %0, t; }" : "=r"(a) : "l"(p));
    return a;
}
__device__ __forceinline__ uint32_t lds32(uint32_t a) {
    uint32_t v;
    asm volatile("ld.shared.b32 %0, [%1];" : "=r"(v) : "r"(a));
    return v;
}
__device__ __forceinline__ uint32_t h2u(__half2 h) {
    uint32_t u;
    __builtin_memcpy(&u, &h, 4);
    return u;
}
__device__ __forceinline__ void mma16(float* d, const uint32_t* a, uint32_t b0, uint32_t b1) {
    asm volatile(
        "mma.sync.aligned.m16n8k16.row.col.f32.f16.f16.f32 "
        "{%0,%1,%2,%3}, {%4,%5,%6,%7}, {%8,%9}, {%0,%1,%2,%3};"
        : "+f"(d[0]), "+f"(d[1]), "+f"(d[2]), "+f"(d[3])
        : "r"(a[0]), "r"(a[1]), "r"(a[2]), "r"(a[3]), "r"(b0), "r"(b1));
}
#define CP_ASYNC16(dst, src) \
    asm volatile("cp.async.cg.shared.global [%0], [%1], 16;" :: "r"(dst), "l"(src))
#define CP_COMMIT() asm volatile("cp.async.commit_group;" ::: "memory")
#define CP_WAIT1()  asm volatile("cp.async.wait_group 1;" ::: "memory")

// Rows: 128B (64 fp16), SW128 swizzle  off = r*128 + (b ^ ((r&7)<<4)).
// Conflict-free for staging chunks and fragment loads (verified R8-R13).
#define STAGE1_SZ 32768   // A(16K) + B1(8K) + B3(8K)
#define STAGE2_SZ 32768   // A(16K) + B(16K)
#define SMEM1_SZ (1024 + 3 * STAGE1_SZ)   // 99328/CTA, occ 2
#define SMEM2_SZ (1024 + 3 * STAGE2_SZ)

// ---------------------------------------------------------------------------
// init: zero routing counters
// ---------------------------------------------------------------------------
__global__ void init_kernel() {
    if (threadIdx.x < NEXP) g_cnt[threadIdx.x] = 0;
    if (threadIdx.x == NEXP) g_done = 0;
}

// ---------------------------------------------------------------------------
// router (+x->fp16 conversion) + scan + scatter (last-CTA pattern)
// 256 CTAs x 256 threads; each warp handles 2 tokens.
// ---------------------------------------------------------------------------
__global__ void __launch_bounds__(256)
router_fused_kernel(const float* __restrict__ x, const float* __restrict__ rw,
                    const float* __restrict__ rb) {
    __shared__ float s_rw[NEXP * DDIM];
    __shared__ int s_last;
    const int tid = threadIdx.x, wid = tid >> 5, lane = tid & 31;

    for (int i = tid; i < NEXP * DDIM / 2; i += 256)
        ((float2*)s_rw)[i] = ((const float2*)rw)[i];
    __syncthreads();

    const int tbase = blockIdx.x * 16 + wid * 2;
#pragma unroll
    for (int j = 0; j < 2; j++) {
        const int t = tbase + j;
        const float* xt = x + (size_t)t * DDIM;
        __half2* xo = (__half2*)(g_xt + (size_t)t * DDIM);
        float acc[NEXP];
#pragma unroll
        for (int e = 0; e < NEXP; e++) acc[e] = 0.f;
        for (int i = lane * 2; i < DDIM; i += 64) {
            const float2 xv = *(const float2*)(xt + i);
            xo[i >> 1] = __floats2half2_rn(xv.x, xv.y);
#pragma unroll
            for (int e = 0; e < NEXP; e++) {
                const float2 wv = *(const float2*)(s_rw + e * DDIM + i);
                acc[e] += xv.x * wv.x + xv.y * wv.y;
            }
        }
#pragma unroll
        for (int off = 16; off; off >>= 1)
#pragma unroll
            for (int e = 0; e < NEXP; e++) acc[e] += __shfl_xor_sync(0xffffffffu, acc[e], off);
        if (lane == 0) {
#pragma unroll
            for (int e = 0; e < NEXP; e++) acc[e] += rb[e];
            int e0 = 0; float l0 = acc[0];
#pragma unroll
            for (int e = 1; e < NEXP; e++) if (acc[e] > l0) { l0 = acc[e]; e0 = e; }
            int e1 = (e0 == 0) ? 1 : 0; float l1 = acc[e1];
#pragma unroll
            for (int e = 0; e < NEXP; e++)
                if (e != e0 && acc[e] > l1) { l1 = acc[e]; e1 = e; }
            float w0 = 1.f / (1.f + __expf(l1 - l0));
            g_tok_e[2 * t] = e0;  g_tok_e[2 * t + 1] = e1;
            g_tok_w[2 * t] = w0;  g_tok_w[2 * t + 1] = 1.f - w0;
            atomicAdd(&g_cnt[e0], 1);
            atomicAdd(&g_cnt[e1], 1);
        }
    }

    __syncthreads();
    if (tid == 0) {
        __threadfence();
        int v = atomicAdd(&g_done, 1);
        s_last = (v == (int)gridDim.x - 1);
    }
    __syncthreads();
    if (!s_last) return;
    __threadfence();

    if (tid == 0) {
        int base = 0, nt = 0;
        for (int e = 0; e < NEXP; e++) {
            g_cur[e] = base;
            int tiles = (g_cnt[e] + 127) >> 7;
            for (int i = 0; i < tiles; i++) { g_tile_e[nt] = e; g_tile_r[nt] = base + i * 128; nt++; }
            base += tiles << 7;
        }
        g_nmt = nt;
        g_done = 0;
    }
    __syncthreads();

    for (int t = tid; t < T_TOKENS; t += 256) {
#pragma unroll
        for (int k = 0; k < 2; k++) {
            int e = g_tok_e[2 * t + k];
            int r = atomicAdd(&g_cur[e], 1);
            g_row_token[r] = t;
            g_tok_row[2 * t + k] = r;
        }
    }
}

// ---------------------------------------------------------------------------
// Weight transposes (+fp16 convert)
// ---------------------------------------------------------------------------
__global__ void transpose13_kernel(const float* __restrict__ w1, const float* __restrict__ w3,
                                   __half* __restrict__ w1t, __half* __restrict__ w3t,
                                   int c_base) {
    __shared__ float t[32][33];
    const int zz = blockIdx.z;
    const float* src = (zz < NEXP) ? w1 : w3;
    __half* dst = (zz < NEXP) ? w1t : w3t;
    const size_t mo = (size_t)(zz & 7) * DDIM * FDIM;
    const int c0 = c_base + blockIdx.x * 32, r0 = blockIdx.y * 32;
    const int tx = threadIdx.x, ty = threadIdx.y;
#pragma unroll
    for (int i = 0; i < 32; i += 8)
        t[ty + i][tx] = src[mo + (size_t)(r0 + ty + i) * FDIM + c0 + tx];
    __syncthreads();
#pragma unroll
    for (int i = 0; i < 32; i += 8)
        dst[mo + (size_t)(c0 + ty + i) * DDIM + r0 + tx] = __float2half_rn(t[tx][ty + i]);
}

__global__ void transpose2_kernel(const float* __restrict__ src, __half* __restrict__ dst) {
    __shared__ float t[32][33];
    const size_t mo = (size_t)blockIdx.z * DDIM * FDIM;
    const int c0 = blockIdx.x * 32, r0 = blockIdx.y * 32;
    const int tx = threadIdx.x, ty = threadIdx.y;
#pragma unroll
    for (int i = 0; i < 32; i += 8)
        t[ty + i][tx] = src[mo + (size_t)(r0 + ty + i) * DDIM + c0 + tx];
    __syncthreads();
#pragma unroll
    for (int i = 0; i < 32; i += 8)
        dst[mo + (size_t)(c0 + ty + i) * FDIM + r0 + tx] = __float2half_rn(t[tx][ty + i]);
}

// ---------------------------------------------------------------------------
// GEMM1 — H = silu(X@w1) * (X@w3)   [fp16 MMA, BK=64, occ 2]  (R13-identical)
// ---------------------------------------------------------------------------
__global__ void __launch_bounds__(256, 2)
gemm1_kernel(int n_base) {
    if (blockIdx.x >= g_nmt) return;
    extern __shared__ char smem[];
    const uint32_t sb = smem_u32(smem);
    const int tid = threadIdx.x, wid = tid >> 5, lane = tid & 31;
    const int wm = wid >> 2, wn = wid & 3;
    const int r4 = lane >> 2, c4 = lane & 3;
    const uint32_t xa = (uint32_t)(r4 << 4);

    const int e  = g_tile_e[blockIdx.x];
    const int r0 = g_tile_r[blockIdx.x];
    const int n0 = n_base + blockIdx.y * 64;

    int* s_tok = (int*)smem;
    if (tid < 128) {
        int t = g_row_token[r0 + tid];
        s_tok[tid] = ((unsigned)t < T_TOKENS) ? t : 0;
    }
    __syncthreads();

    const __half* w1e = g_w1t + (size_t)e * FDIM * DDIM + (size_t)n0 * DDIM;
    const ptrdiff_t d31 = (const char*)g_w3t - (const char*)g_w1t;

    const char* srcA[4]; const char* srcB1[2];
    uint32_t dOfA[4], dOfB[2];
#pragma unroll
    for (int i = 0; i < 4; i++) {
        int idx = tid + i * 256;
        int row = idx >> 3, c = idx & 7;
        dOfA[i] = (uint32_t)(row * 128 + ((c * 16) ^ ((row & 7) << 4)));
        srcA[i] = (const char*)(g_xt + (size_t)s_tok[row] * DDIM + c * 8);
    }
#pragma unroll
    for (int i = 0; i < 2; i++) {
        int idx = tid + i * 256;
        int row = idx >> 3, c = idx & 7;
        dOfB[i] = (uint32_t)(row * 128 + ((c * 16) ^ ((row & 7) << 4)));
        srcB1[i] = (const char*)(w1e + (size_t)row * DDIM + c * 8);
    }

    float accU[4][2][4], accV[4][2][4];
#pragma unroll
    for (int i = 0; i < 4; i++)
#pragma unroll
        for (int j = 0; j < 2; j++)
#pragma unroll
            for (int q = 0; q < 4; q++) { accU[i][j][q] = 0.f; accV[i][j][q] = 0.f; }

    const int KS = DDIM / BK;   // 16

#define G1_ISSUE(s)                                                            \
    do {                                                                       \
        uint32_t base_ = sb + 1024 + ((s) % 3) * STAGE1_SZ;                    \
        size_t off_ = (size_t)(s) * 128;                                       \
        _Pragma("unroll")                                                      \
        for (int i_ = 0; i_ < 4; i_++)                                         \
            CP_ASYNC16(base_ + dOfA[i_], srcA[i_] + off_);                     \
        _Pragma("unroll")                                                      \
        for (int i_ = 0; i_ < 2; i_++) {                                       \
            CP_ASYNC16(base_ + 16384 + dOfB[i_], srcB1[i_] + off_);            \
            CP_ASYNC16(base_ + 24576 + dOfB[i_], srcB1[i_] + d31 + off_);      \
        }                                                                      \
    } while (0)

    G1_ISSUE(0); CP_COMMIT();
    G1_ISSUE(1); CP_COMMIT();

    for (int ks = 0; ks < KS; ks++) {
        CP_WAIT1();
        __syncthreads();
        if (ks + 2 < KS) G1_ISSUE(ks + 2);
        CP_COMMIT();

        const uint32_t sA  = sb + 1024 + (ks % 3) * STAGE1_SZ;
        const uint32_t sB1 = sA + 16384;
        const uint32_t sB3 = sA + 24576;
#pragma unroll
        for (int g = 0; g < 4; g++) {
            const uint32_t kb = (uint32_t)(g * 32 + 4 * c4);
            const uint32_t k0 = kb ^ xa;
            const uint32_t k1 = (kb + 16) ^ xa;
            uint32_t a[4][4], b1f[2][2], b3f[2][2];
#pragma unroll
            for (int mt = 0; mt < 4; mt++) {
                uint32_t rowb = sA + (uint32_t)((wm * 64 + mt * 16 + r4) * 128);
                a[mt][0] = lds32(rowb + k0);
                a[mt][1] = lds32(rowb + 1024 + k0);
                a[mt][2] = lds32(rowb + k1);
                a[mt][3] = lds32(rowb + 1024 + k1);
            }
#pragma unroll
            for (int nt = 0; nt < 2; nt++) {
                uint32_t nrow = (uint32_t)((wn * 16 + nt * 8 + r4) * 128);
                b1f[nt][0] = lds32(sB1 + nrow + k0);
                b1f[nt][1] = lds32(sB1 + nrow + k1);
                b3f[nt][0] = lds32(sB3 + nrow + k0);
                b3f[nt][1] = lds32(sB3 + nrow + k1);
            }
#pragma unroll
            for (int nt = 0; nt < 2; nt++)
#pragma unroll
                for (int mt = 0; mt < 4; mt++) {
                    mma16(accU[mt][nt], a[mt], b1f[nt][0], b1f[nt][1]);
                    mma16(accV[mt][nt], a[mt], b3f[nt][0], b3f[nt][1]);
                }
        }
    }

#pragma unroll
    for (int mt = 0; mt < 4; mt++) {
#pragma unroll
        for (int nt = 0; nt < 2; nt++) {
#pragma unroll
            for (int half = 0; half < 2; half++) {
                int r = r0 + wm * 64 + mt * 16 + r4 + half * 8;
                int cgl = n0 + wn * 16 + nt * 8 + 2 * c4;
                float u0 = accU[mt][nt][2 * half],     v0 = accV[mt][nt][2 * half];
                float u1 = accU[mt][nt][2 * half + 1], v1 = accV[mt][nt][2 * half + 1];
                __half2 o = __floats2half2_rn(u0 / (1.f + __expf(-u0)) * v0,
                                              u1 / (1.f + __expf(-u1)) * v1);
                *(__half2*)(g_H + (size_t)r * FDIM + cgl) = o;
            }
        }
    }
}

// ---------------------------------------------------------------------------
// GEMM2 (split-K) — Yout = H[:, k_base:+2048] @ w2t[:, :, k_base:+2048]
// [fp16 MMA, BK=64, occ 2]  (R13-identical)
// ---------------------------------------------------------------------------
__global__ void __launch_bounds__(256, 2)
gemm2_kernel(int k_base, float* __restrict__ Yout) {
    if (blockIdx.x >= g_nmt) return;
    extern __shared__ char smem[];
    const uint32_t sb = smem_u32(smem);
    const int tid = threadIdx.x, wid = tid >> 5, lane = tid & 31;
    const int wm = wid >> 2, wn = wid & 3;
    const int r4 = lane >> 2, c4 = lane & 3;
    const uint32_t xa = (uint32_t)(r4 << 4);

    const int e  = g_tile_e[blockIdx.x];
    const int r0 = g_tile_r[blockIdx.x];
    const int n0 = blockIdx.y * 128;

    const __half* w2e = g_w2t + (size_t)e * DDIM * FDIM + (size_t)n0 * FDIM + k_base;

    const char* srcA[4]; const char* srcB[4];
    uint32_t dOf[4];
#pragma unroll
    for (int i = 0; i < 4; i++) {
        int idx = tid + i * 256;
        int row = idx >> 3, c = idx & 7;
        dOf[i] = (uint32_t)(row * 128 + ((c * 16) ^ ((row & 7) << 4)));
        srcA[i] = (const char*)(g_H + (size_t)(r0 + row) * FDIM + k_base + c * 8);
        srcB[i] = (const char*)(w2e + (size_t)row * FDIM + c * 8);
    }

    float acc[4][4][4];
#pragma unroll
    for (int i = 0; i < 4; i++)
#pragma unroll
        for (int j = 0; j < 4; j++)
#pragma unroll
            for (int q = 0; q < 4; q++) acc[i][j][q] = 0.f;

    const int KS = (FDIM / 2) / BK;   // 32

#define G2_ISSUE(s)                                                            \
    do {                                                                       \
        uint32_t base_ = sb + 1024 + ((s) % 3) * STAGE2_SZ;                    \
        size_t off_ = (size_t)(s) * 128;                                       \
        _Pragma("unroll")                                                      \
        for (int i_ = 0; i_ < 4; i_++) {                                       \
            CP_ASYNC16(base_ + dOf[i_],         srcA[i_] + off_);              \
            CP_ASYNC16(base_ + 16384 + dOf[i_], srcB[i_] + off_);              \
        }                                                                      \
    } while (0)

    G2_ISSUE(0); CP_COMMIT();
    G2_ISSUE(1); CP_COMMIT();

    for (int ks = 0; ks < KS; ks++) {
        CP_WAIT1();
        __syncthreads();
        if (ks + 2 < KS) G2_ISSUE(ks + 2);
        CP_COMMIT();

        const uint32_t sA = sb + 1024 + (ks % 3) * STAGE2_SZ;
        const uint32_t sB = sA + 16384;
#pragma unroll
        for (int g = 0; g < 4; g++) {
            const uint32_t kb = (uint32_t)(g * 32 + 4 * c4);
            const uint32_t k0 = kb ^ xa;
            const uint32_t k1 = (kb + 16) ^ xa;
            uint32_t a[4][4], bf[4][2];
#pragma unroll
            for (int mt = 0; mt < 4; mt++) {
                uint32_t rowb = sA + (uint32_t)((wm * 64 + mt * 16 + r4) * 128);
                a[mt][0] = lds32(rowb + k0);
                a[mt][1] = lds32(rowb + 1024 + k0);
                a[mt][2] = lds32(rowb + k1);
                a[mt][3] = lds32(rowb + 1024 + k1);
            }
#pragma unroll
            for (int nt = 0; nt < 4; nt++) {
                uint32_t nrow = (uint32_t)((wn * 32 + nt * 8 + r4) * 128);
                bf[nt][0] = lds32(sB + nrow + k0);
                bf[nt][1] = lds32(sB + nrow + k1);
            }
#pragma unroll
            for (int nt = 0; nt < 4; nt++)
#pragma unroll
                for (int mt = 0; mt < 4; mt++)
                    mma16(acc[mt][nt], a[mt], bf[nt][0], bf[nt][1]);
        }
    }

#pragma unroll
    for (int mt = 0; mt < 4; mt++) {
#pragma unroll
        for (int nt = 0; nt < 4; nt++) {
#pragma unroll
            for (int half = 0; half < 2; half++) {
                int r = r0 + wm * 64 + mt * 16 + r4 + half * 8;
                int cgl = n0 + wn * 32 + nt * 8 + 2 * c4;
                float2 o;
                o.x = acc[mt][nt][2 * half];
                o.y = acc[mt][nt][2 * half + 1];
                *(float2*)(Yout + (size_t)r * DDIM + cgl) = o;
            }
        }
    }
}

// ---------------------------------------------------------------------------
// combine — out[t] = w0*(Y1[r0]+Y2[r0]) + w1*(Y1[r1]+Y2[r1])
// ---------------------------------------------------------------------------
__global__ void combine_kernel(float* __restrict__ out) {
    int t = blockIdx.x;
    int d = threadIdx.x * 4;
    float w0 = g_tok_w[2 * t], w1v = g_tok_w[2 * t + 1];
    int   r0 = g_tok_row[2 * t], r1 = g_tok_row[2 * t + 1];
    const float4 a1 = *(const float4*)(g_Y1 + (size_t)r0 * DDIM + d);
    const float4 a2 = *(const float4*)(g_Y2 + (size_t)r0 * DDIM + d);
    const float4 b1 = *(const float4*)(g_Y1 + (size_t)r1 * DDIM + d);
    const float4 b2 = *(const float4*)(g_Y2 + (size_t)r1 * DDIM + d);
    float4 o;
    o.x = w0 * (a1.x + a2.x) + w1v * (b1.x + b2.x);
    o.y = w0 * (a1.y + a2.y) + w1v * (b1.y + b2.y);
    o.z = w0 * (a1.z + a2.z) + w1v * (b1.z + b2.z);
    o.w = w0 * (a1.w + a2.w) + w1v * (b1.w + b2.w);
    *(float4*)(out + (size_t)t * DDIM + d) = o;
}

// ---------------------------------------------------------------------------
// Launcher — cross-stream GEMM pairing to fill fractional waves.
// main: init, router, g1a, g2b, combine
// s1:   t13a, t13b, t2, g1b, g2a
// g1a ∥ g1b (disjoint H columns), g2a ∥ g2b (disjoint Y buffers).
// ---------------------------------------------------------------------------
extern "C" void kernel_launch(void* const* d_in, const int* in_sizes, int n_in,
                              void* d_out, int out_size) {
    const float* x  = (const float*)d_in[0];
    const float* rw = (const float*)d_in[1];
    const float* rb = (const float*)d_in[2];
    const float* w1 = (const float*)d_in[3];
    const float* w2 = (const float*)d_in[4];
    const float* w3 = (const float*)d_in[5];
    float* out = (float*)d_out;

    cudaFuncSetAttribute(gemm1_kernel, cudaFuncAttributeMaxDynamicSharedMemorySize, SMEM1_SZ);
    cudaFuncSetAttribute(gemm2_kernel, cudaFuncAttributeMaxDynamicSharedMemorySize, SMEM2_SZ);

    __half *w1t, *w3t, *w2t;
    float *y1, *y2;
    cudaGetSymbolAddress((void**)&w1t, g_w1t);
    cudaGetSymbolAddress((void**)&w3t, g_w3t);
    cudaGetSymbolAddress((void**)&w2t, g_w2t);
    cudaGetSymbolAddress((void**)&y1, g_Y1);
    cudaGetSymbolAddress((void**)&y2, g_Y2);

    cudaStream_t s1;
    cudaEvent_t e0, e13a, er, eg1a, eg1b, eg2a;
    cudaStreamCreateWithFlags(&s1, cudaStreamNonBlocking);
    cudaEventCreateWithFlags(&e0,   cudaEventDisableTiming);
    cudaEventCreateWithFlags(&e13a, cudaEventDisableTiming);
    cudaEventCreateWithFlags(&er,   cudaEventDisableTiming);
    cudaEventCreateWithFlags(&eg1a, cudaEventDisableTiming);
    cudaEventCreateWithFlags(&eg1b, cudaEventDisableTiming);
    cudaEventCreateWithFlags(&eg2a, cudaEventDisableTiming);

    cudaEventRecord(e0, 0);
    cudaStreamWaitEvent(s1, e0, 0);

    init_kernel<<<1, 32>>>();                                                // #1 main
    transpose13_kernel<<<dim3(64, DDIM / 32, 2 * NEXP), dim3(32, 8), 0, s1>>>(
        w1, w3, w1t, w3t, 0);                                                // #2 s1 (F 0..2047)
    cudaEventRecord(e13a, s1);
    router_fused_kernel<<<256, 256>>>(x, rw, rb);                            // #3 main (+x->fp16)
    cudaEventRecord(er, 0);

    cudaStreamWaitEvent(0, e13a, 0);
    gemm1_kernel<<<dim3(MAX_MT, 32), 256, SMEM1_SZ>>>(0);                    // #4 main (profiled)
    cudaEventRecord(eg1a, 0);

    transpose13_kernel<<<dim3(64, DDIM / 32, 2 * NEXP), dim3(32, 8), 0, s1>>>(
        w1, w3, w1t, w3t, 2048);                                             // #5 s1
    transpose2_kernel<<<dim3(DDIM / 32, FDIM / 32, NEXP), dim3(32, 8), 0, s1>>>(
        w2, w2t);                                                            // #6 s1

    // g1b on s1: needs t13b (s1 order) + router (er) — runs ∥ g1a
    cudaStreamWaitEvent(s1, er, 0);
    gemm1_kernel<<<dim3(MAX_MT, 32), 256, SMEM1_SZ, s1>>>(2048);             // #7 s1
    cudaEventRecord(eg1b, s1);

    // g2a on s1: needs g1a (eg1a) + t2 (s1 order) — runs ∥ g2b
    cudaStreamWaitEvent(s1, eg1a, 0);
    gemm2_kernel<<<dim3(MAX_MT, DDIM / 128), 256, SMEM2_SZ, s1>>>(0, y1);    // #8 s1
    cudaEventRecord(eg2a, s1);

    // g2b on main: needs g1b (eg1b; implies t2 complete via s1 order)
    cudaStreamWaitEvent(0, eg1b, 0);
    gemm2_kernel<<<dim3(MAX_MT, DDIM / 128), 256, SMEM2_SZ>>>(2048, y2);     // #9 main

    // combine: needs g2b (main order) + g2a (eg2a)
    cudaStreamWaitEvent(0, eg2a, 0);
    combine_kernel<<<T_TOKENS, 256>>>(out);                                  // #10 main
}

// round 15
// speedup vs baseline: 1.5374x; 1.5374x over previous
#include <cuda_runtime.h>
#include <cuda_fp16.h>
#include <cstdint>

// ---------------------------------------------------------------------------
// Problem constants
// ---------------------------------------------------------------------------
#define T_TOKENS 4096
#define DDIM 1024
#define FDIM 4096
#define NEXP 8
#define BM 128
#define BK 64
#define MAX_MT 72
#define ROWS_CAP (MAX_MT * 128)

// ---------------------------------------------------------------------------
// Device scratch (fp16 operands, fp32 outputs)
// ---------------------------------------------------------------------------
__device__ int    g_cnt[NEXP];
__device__ int    g_cur[NEXP];
__device__ int    g_done;
__device__ int    g_nmt;
__device__ int    g_tile_e[MAX_MT];
__device__ int    g_tile_r[MAX_MT];
__device__ int    g_row_token[ROWS_CAP];
__device__ int    g_tok_e[T_TOKENS * 2];
__device__ int    g_tok_row[T_TOKENS * 2];
__device__ float  g_tok_w[T_TOKENS * 2];
__device__ __half g_H[(size_t)ROWS_CAP * FDIM];
__device__ float  g_Y1[(size_t)ROWS_CAP * DDIM];
__device__ float  g_Y2[(size_t)ROWS_CAP * DDIM];
__device__ __half g_xt[(size_t)T_TOKENS * DDIM];
__device__ __half g_w1t[(size_t)NEXP * DDIM * FDIM];
__device__ __half g_w3t[(size_t)NEXP * DDIM * FDIM];
__device__ __half g_w2t[(size_t)NEXP * DDIM * FDIM];

// ---------------------------------------------------------------------------
// Helpers
// ---------------------------------------------------------------------------
__device__ __forceinline__ uint32_t smem_u32(const void* p) {
    uint32_t a;
    asm("{ .reg .u64 t; cvta.to.shared.u64 t, %1; cvt.u32.u64 %0, t; }" : "=r"(a) : "l"(p));
    return a;
}
__device__ __forceinline__ uint32_t lds32(uint32_t a) {
    uint32_t v;
    asm volatile("ld.shared.b32 %0, [%1];" : "=r"(v) : "r"(a));
    return v;
}
__device__ __forceinline__ uint32_t h2u(__half2 h) {
    uint32_t u;
    __builtin_memcpy(&u, &h, 4);
    return u;
}
__device__ __forceinline__ void mma16(float* d, const uint32_t* a, uint32_t b0, uint32_t b1) {
    asm volatile(
        "mma.sync.aligned.m16n8k16.row.col.f32.f16.f16.f32 "
        "{%0,%1,%2,%3}, {%4,%5,%6,%7}, {%8,%9}, {%0,%1,%2,%3};"
        : "+f"(d[0]), "+f"(d[1]), "+f"(d[2]), "+f"(d[3])
        : "r"(a[0]), "r"(a[1]), "r"(a[2]), "r"(a[3]), "r"(b0), "r"(b1));
}
#define CP_ASYNC16(dst, src) \
    asm volatile("cp.async.cg.shared.global [%0], [%1], 16;" :: "r"(dst), "l"(src))
#define CP_COMMIT() asm volatile("cp.async.commit_group;" ::: "memory")
#define CP_WAIT1()  asm volatile("cp.async.wait_group 1;" ::: "memory")

// Rows: 128B (64 fp16), SW128 swizzle  off = r*128 + (b ^ ((r&7)<<4)).
// Conflict-free for staging chunks and fragment loads (verified R8-R13).
#define STAGE1_SZ 32768   // A(16K) + B1(8K) + B3(8K)
#define STAGE2_SZ 32768   // A(16K) + B(16K)
#define SMEM1_SZ (1024 + 3 * STAGE1_SZ)   // 99328/CTA, occ 2
#define SMEM2_SZ (1024 + 3 * STAGE2_SZ)

// ---------------------------------------------------------------------------
// init: zero routing counters
// ---------------------------------------------------------------------------
__global__ void init_kernel() {
    if (threadIdx.x < NEXP) g_cnt[threadIdx.x] = 0;
    if (threadIdx.x == NEXP) g_done = 0;
}

// ---------------------------------------------------------------------------
// router (+x->fp16 conversion) + scan + scatter (last-CTA pattern)
// 256 CTAs x 256 threads; each warp handles 2 tokens.
// ---------------------------------------------------------------------------
__global__ void __launch_bounds__(256)
router_fused_kernel(const float* __restrict__ x, const float* __restrict__ rw,
                    const float* __restrict__ rb) {
    __shared__ float s_rw[NEXP * DDIM];
    __shared__ int s_last;
    const int tid = threadIdx.x, wid = tid >> 5, lane = tid & 31;

    for (int i = tid; i < NEXP * DDIM / 2; i += 256)
        ((float2*)s_rw)[i] = ((const float2*)rw)[i];
    __syncthreads();

    const int tbase = blockIdx.x * 16 + wid * 2;
#pragma unroll
    for (int j = 0; j < 2; j++) {
        const int t = tbase + j;
        const float* xt = x + (size_t)t * DDIM;
        __half2* xo = (__half2*)(g_xt + (size_t)t * DDIM);
        float acc[NEXP];
#pragma unroll
        for (int e = 0; e < NEXP; e++) acc[e] = 0.f;
        for (int i = lane * 2; i < DDIM; i += 64) {
            const float2 xv = *(const float2*)(xt + i);
            xo[i >> 1] = __floats2half2_rn(xv.x, xv.y);
#pragma unroll
            for (int e = 0; e < NEXP; e++) {
                const float2 wv = *(const float2*)(s_rw + e * DDIM + i);
                acc[e] += xv.x * wv.x + xv.y * wv.y;
            }
        }
#pragma unroll
        for (int off = 16; off; off >>= 1)
#pragma unroll
            for (int e = 0; e < NEXP; e++) acc[e] += __shfl_xor_sync(0xffffffffu, acc[e], off);
        if (lane == 0) {
#pragma unroll
            for (int e = 0; e < NEXP; e++) acc[e] += rb[e];
            int e0 = 0; float l0 = acc[0];
#pragma unroll
            for (int e = 1; e < NEXP; e++) if (acc[e] > l0) { l0 = acc[e]; e0 = e; }
            int e1 = (e0 == 0) ? 1 : 0; float l1 = acc[e1];
#pragma unroll
            for (int e = 0; e < NEXP; e++)
                if (e != e0 && acc[e] > l1) { l1 = acc[e]; e1 = e; }
            float w0 = 1.f / (1.f + __expf(l1 - l0));
            g_tok_e[2 * t] = e0;  g_tok_e[2 * t + 1] = e1;
            g_tok_w[2 * t] = w0;  g_tok_w[2 * t + 1] = 1.f - w0;
            atomicAdd(&g_cnt[e0], 1);
            atomicAdd(&g_cnt[e1], 1);
        }
    }

    __syncthreads();
    if (tid == 0) {
        __threadfence();
        int v = atomicAdd(&g_done, 1);
        s_last = (v == (int)gridDim.x - 1);
    }
    __syncthreads();
    if (!s_last) return;
    __threadfence();

    if (tid == 0) {
        int base = 0, nt = 0;
        for (int e = 0; e < NEXP; e++) {
            g_cur[e] = base;
            int tiles = (g_cnt[e] + 127) >> 7;
            for (int i = 0; i < tiles; i++) { g_tile_e[nt] = e; g_tile_r[nt] = base + i * 128; nt++; }
            base += tiles << 7;
        }
        g_nmt = nt;
        g_done = 0;
    }
    __syncthreads();

    for (int t = tid; t < T_TOKENS; t += 256) {
#pragma unroll
        for (int k = 0; k < 2; k++) {
            int e = g_tok_e[2 * t + k];
            int r = atomicAdd(&g_cur[e], 1);
            g_row_token[r] = t;
            g_tok_row[2 * t + k] = r;
        }
    }
}

// ---------------------------------------------------------------------------
// Weight transposes (+fp16 convert) — forked stream; transpose13 split by F-half
// ---------------------------------------------------------------------------
__global__ void transpose13_kernel(const float* __restrict__ w1, const float* __restrict__ w3,
                                   __half* __restrict__ w1t, __half* __restrict__ w3t,
                                   int c_base) {
    __shared__ float t[32][33];
    const int zz = blockIdx.z;
    const float* src = (zz < NEXP) ? w1 : w3;
    __half* dst = (zz < NEXP) ? w1t : w3t;
    const size_t mo = (size_t)(zz & 7) * DDIM * FDIM;
    const int c0 = c_base + blockIdx.x * 32, r0 = blockIdx.y * 32;
    const int tx = threadIdx.x, ty = threadIdx.y;
#pragma unroll
    for (int i = 0; i < 32; i += 8)
        t[ty + i][tx] = src[mo + (size_t)(r0 + ty + i) * FDIM + c0 + tx];
    __syncthreads();
#pragma unroll
    for (int i = 0; i < 32; i += 8)
        dst[mo + (size_t)(c0 + ty + i) * DDIM + r0 + tx] = __float2half_rn(t[tx][ty + i]);
}

__global__ void transpose2_kernel(const float* __restrict__ src, __half* __restrict__ dst) {
    __shared__ float t[32][33];
    const size_t mo = (size_t)blockIdx.z * DDIM * FDIM;
    const int c0 = blockIdx.x * 32, r0 = blockIdx.y * 32;
    const int tx = threadIdx.x, ty = threadIdx.y;
#pragma unroll
    for (int i = 0; i < 32; i += 8)
        t[ty + i][tx] = src[mo + (size_t)(r0 + ty + i) * DDIM + c0 + tx];
    __syncthreads();
#pragma unroll
    for (int i = 0; i < 32; i += 8)
        dst[mo + (size_t)(c0 + ty + i) * FDIM + r0 + tx] = __float2half_rn(t[tx][ty + i]);
}

// ---------------------------------------------------------------------------
// GEMM1 — H = silu(X@w1) * (X@w3)   [fp16 MMA, BK=64, occ 2]
// CTA tile 128x64, 8 warps (2M x 4N), warp tile 64x16.
// ---------------------------------------------------------------------------
__global__ void __launch_bounds__(256, 2)
gemm1_kernel(int n_base) {
    if (blockIdx.x >= g_nmt) return;
    extern __shared__ char smem[];
    const uint32_t sb = smem_u32(smem);
    const int tid = threadIdx.x, wid = tid >> 5, lane = tid & 31;
    const int wm = wid >> 2, wn = wid & 3;
    const int r4 = lane >> 2, c4 = lane & 3;
    const uint32_t xa = (uint32_t)(r4 << 4);

    const int e  = g_tile_e[blockIdx.x];
    const int r0 = g_tile_r[blockIdx.x];
    const int n0 = n_base + blockIdx.y * 64;

    int* s_tok = (int*)smem;
    if (tid < 128) {
        int t = g_row_token[r0 + tid];
        s_tok[tid] = ((unsigned)t < T_TOKENS) ? t : 0;
    }
    __syncthreads();

    const __half* w1e = g_w1t + (size_t)e * FDIM * DDIM + (size_t)n0 * DDIM;
    const ptrdiff_t d31 = (const char*)g_w3t - (const char*)g_w1t;

    const char* srcA[4]; const char* srcB1[2];
    uint32_t dOfA[4], dOfB[2];
#pragma unroll
    for (int i = 0; i < 4; i++) {
        int idx = tid + i * 256;
        int row = idx >> 3, c = idx & 7;
        dOfA[i] = (uint32_t)(row * 128 + ((c * 16) ^ ((row & 7) << 4)));
        srcA[i] = (const char*)(g_xt + (size_t)s_tok[row] * DDIM + c * 8);
    }
#pragma unroll
    for (int i = 0; i < 2; i++) {
        int idx = tid + i * 256;
        int row = idx >> 3, c = idx & 7;
        dOfB[i] = (uint32_t)(row * 128 + ((c * 16) ^ ((row & 7) << 4)));
        srcB1[i] = (const char*)(w1e + (size_t)row * DDIM + c * 8);
    }

    float accU[4][2][4], accV[4][2][4];
#pragma unroll
    for (int i = 0; i < 4; i++)
#pragma unroll
        for (int j = 0; j < 2; j++)
#pragma unroll
            for (int q = 0; q < 4; q++) { accU[i][j][q] = 0.f; accV[i][j][q] = 0.f; }

    const int KS = DDIM / BK;   // 16

#define G1_ISSUE(s)                                                            \
    do {                                                                       \
        uint32_t base_ = sb + 1024 + ((s) % 3) * STAGE1_SZ;                    \
        size_t off_ = (size_t)(s) * 128;                                       \
        _Pragma("unroll")                                                      \
        for (int i_ = 0; i_ < 4; i_++)                                         \
            CP_ASYNC16(base_ + dOfA[i_], srcA[i_] + off_);                     \
        _Pragma("unroll")                                                      \
        for (int i_ = 0; i_ < 2; i_++) {                                       \
            CP_ASYNC16(base_ + 16384 + dOfB[i_], srcB1[i_] + off_);            \
            CP_ASYNC16(base_ + 24576 + dOfB[i_], srcB1[i_] + d31 + off_);      \
        }                                                                      \
    } while (0)

    G1_ISSUE(0); CP_COMMIT();
    G1_ISSUE(1); CP_COMMIT();

    for (int ks = 0; ks < KS; ks++) {
        CP_WAIT1();
        __syncthreads();
        if (ks + 2 < KS) G1_ISSUE(ks + 2);
        CP_COMMIT();

        const uint32_t sA  = sb + 1024 + (ks % 3) * STAGE1_SZ;
        const uint32_t sB1 = sA + 16384;
        const uint32_t sB3 = sA + 24576;
#pragma unroll
        for (int g = 0; g < 4; g++) {
            const uint32_t kb = (uint32_t)(g * 32 + 4 * c4);
            const uint32_t k0 = kb ^ xa;
            const uint32_t k1 = (kb + 16) ^ xa;
            uint32_t a[4][4], b1f[2][2], b3f[2][2];
#pragma unroll
            for (int mt = 0; mt < 4; mt++) {
                uint32_t rowb = sA + (uint32_t)((wm * 64 + mt * 16 + r4) * 128);
                a[mt][0] = lds32(rowb + k0);
                a[mt][1] = lds32(rowb + 1024 + k0);
                a[mt][2] = lds32(rowb + k1);
                a[mt][3] = lds32(rowb + 1024 + k1);
            }
#pragma unroll
            for (int nt = 0; nt < 2; nt++) {
                uint32_t nrow = (uint32_t)((wn * 16 + nt * 8 + r4) * 128);
                b1f[nt][0] = lds32(sB1 + nrow + k0);
                b1f[nt][1] = lds32(sB1 + nrow + k1);
                b3f[nt][0] = lds32(sB3 + nrow + k0);
                b3f[nt][1] = lds32(sB3 + nrow + k1);
            }
#pragma unroll
            for (int nt = 0; nt < 2; nt++)
#pragma unroll
                for (int mt = 0; mt < 4; mt++) {
                    mma16(accU[mt][nt], a[mt], b1f[nt][0], b1f[nt][1]);
                    mma16(accV[mt][nt], a[mt], b3f[nt][0], b3f[nt][1]);
                }
        }
    }

#pragma unroll
    for (int mt = 0; mt < 4; mt++) {
#pragma unroll
        for (int nt = 0; nt < 2; nt++) {
#pragma unroll
            for (int half = 0; half < 2; half++) {
                int r = r0 + wm * 64 + mt * 16 + r4 + half * 8;
                int cgl = n0 + wn * 16 + nt * 8 + 2 * c4;
                float u0 = accU[mt][nt][2 * half],     v0 = accV[mt][nt][2 * half];
                float u1 = accU[mt][nt][2 * half + 1], v1 = accV[mt][nt][2 * half + 1];
                __half2 o = __floats2half2_rn(u0 / (1.f + __expf(-u0)) * v0,
                                              u1 / (1.f + __expf(-u1)) * v1);
                *(__half2*)(g_H + (size_t)r * FDIM + cgl) = o;
            }
        }
    }
}

// ---------------------------------------------------------------------------
// GEMM2 (split-K) — Yout = H[:, k_base:+2048] @ w2t[:, :, k_base:+2048]
// [fp16 MMA, BK=64, occ 2]
// ---------------------------------------------------------------------------
__global__ void __launch_bounds__(256, 2)
gemm2_kernel(int k_base, float* __restrict__ Yout) {
    if (blockIdx.x >= g_nmt) return;
    extern __shared__ char smem[];
    const uint32_t sb = smem_u32(smem);
    const int tid = threadIdx.x, wid = tid >> 5, lane = tid & 31;
    const int wm = wid >> 2, wn = wid & 3;
    const int r4 = lane >> 2, c4 = lane & 3;
    const uint32_t xa = (uint32_t)(r4 << 4);

    const int e  = g_tile_e[blockIdx.x];
    const int r0 = g_tile_r[blockIdx.x];
    const int n0 = blockIdx.y * 128;

    const __half* w2e = g_w2t + (size_t)e * DDIM * FDIM + (size_t)n0 * FDIM + k_base;

    const char* srcA[4]; const char* srcB[4];
    uint32_t dOf[4];
#pragma unroll
    for (int i = 0; i < 4; i++) {
        int idx = tid + i * 256;
        int row = idx >> 3, c = idx & 7;
        dOf[i] = (uint32_t)(row * 128 + ((c * 16) ^ ((row & 7) << 4)));
        srcA[i] = (const char*)(g_H + (size_t)(r0 + row) * FDIM + k_base + c * 8);
        srcB[i] = (const char*)(w2e + (size_t)row * FDIM + c * 8);
    }

    float acc[4][4][4];
#pragma unroll
    for (int i = 0; i < 4; i++)
#pragma unroll
        for (int j = 0; j < 4; j++)
#pragma unroll
            for (int q = 0; q < 4; q++) acc[i][j][q] = 0.f;

    const int KS = (FDIM / 2) / BK;   // 32

#define G2_ISSUE(s)                                                            \
    do {                                                                       \
        uint32_t base_ = sb + 1024 + ((s) % 3) * STAGE2_SZ;                    \
        size_t off_ = (size_t)(s) * 128;                                       \
        _Pragma("unroll")                                                      \
        for (int i_ = 0; i_ < 4; i_++) {                                       \
            CP_ASYNC16(base_ + dOf[i_],         srcA[i_] + off_);              \
            CP_ASYNC16(base_ + 16384 + dOf[i_], srcB[i_] + off_);              \
        }                                                                      \
    } while (0)

    G2_ISSUE(0); CP_COMMIT();
    G2_ISSUE(1); CP_COMMIT();

    for (int ks = 0; ks < KS; ks++) {
        CP_WAIT1();
        __syncthreads();
        if (ks + 2 < KS) G2_ISSUE(ks + 2);
        CP_COMMIT();

        const uint32_t sA = sb + 1024 + (ks % 3) * STAGE2_SZ;
        const uint32_t sB = sA + 16384;
#pragma unroll
        for (int g = 0; g < 4; g++) {
            const uint32_t kb = (uint32_t)(g * 32 + 4 * c4);
            const uint32_t k0 = kb ^ xa;
            const uint32_t k1 = (kb + 16) ^ xa;
            uint32_t a[4][4], bf[4][2];
#pragma unroll
            for (int mt = 0; mt < 4; mt++) {
                uint32_t rowb = sA + (uint32_t)((wm * 64 + mt * 16 + r4) * 128);
                a[mt][0] = lds32(rowb + k0);
                a[mt][1] = lds32(rowb + 1024 + k0);
                a[mt][2] = lds32(rowb + k1);
                a[mt][3] = lds32(rowb + 1024 + k1);
            }
#pragma unroll
            for (int nt = 0; nt < 4; nt++) {
                uint32_t nrow = (uint32_t)((wn * 32 + nt * 8 + r4) * 128);
                bf[nt][0] = lds32(sB + nrow + k0);
                bf[nt][1] = lds32(sB + nrow + k1);
            }
#pragma unroll
            for (int nt = 0; nt < 4; nt++)
#pragma unroll
                for (int mt = 0; mt < 4; mt++)
                    mma16(acc[mt][nt], a[mt], bf[nt][0], bf[nt][1]);
        }
    }

#pragma unroll
    for (int mt = 0; mt < 4; mt++) {
#pragma unroll
        for (int nt = 0; nt < 4; nt++) {
#pragma unroll
            for (int half = 0; half < 2; half++) {
                int r = r0 + wm * 64 + mt * 16 + r4 + half * 8;
                int cgl = n0 + wn * 32 + nt * 8 + 2 * c4;
                float2 o;
                o.x = acc[mt][nt][2 * half];
                o.y = acc[mt][nt][2 * half + 1];
                *(float2*)(Yout + (size_t)r * DDIM + cgl) = o;
            }
        }
    }
}

// ---------------------------------------------------------------------------
// combine — out[t] = w0*(Y1[r0]+Y2[r0]) + w1*(Y1[r1]+Y2[r1])
// ---------------------------------------------------------------------------
__global__ void combine_kernel(float* __restrict__ out) {
    int t = blockIdx.x;
    int d = threadIdx.x * 4;
    float w0 = g_tok_w[2 * t], w1v = g_tok_w[2 * t + 1];
    int   r0 = g_tok_row[2 * t], r1 = g_tok_row[2 * t + 1];
    const float4 a1 = *(const float4*)(g_Y1 + (size_t)r0 * DDIM + d);
    const float4 a2 = *(const float4*)(g_Y2 + (size_t)r0 * DDIM + d);
    const float4 b1 = *(const float4*)(g_Y1 + (size_t)r1 * DDIM + d);
    const float4 b2 = *(const float4*)(g_Y2 + (size_t)r1 * DDIM + d);
    float4 o;
    o.x = w0 * (a1.x + a2.x) + w1v * (b1.x + b2.x);
    o.y = w0 * (a1.y + a2.y) + w1v * (b1.y + b2.y);
    o.z = w0 * (a1.z + a2.z) + w1v * (b1.z + b2.z);
    o.w = w0 * (a1.w + a2.w) + w1v * (b1.w + b2.w);
    *(float4*)(out + (size_t)t * DDIM + d) = o;
}

// ---------------------------------------------------------------------------
// Launcher — R13 schedule (validated best).
// s1: t13a, t13b, t2, gemm2a — gemm2a || gemm1b.
// main: init, router(+convx), gemm1a, gemm1b, gemm2b, combine.
// ---------------------------------------------------------------------------
extern "C" void kernel_launch(void* const* d_in, const int* in_sizes, int n_in,
                              void* d_out, int out_size) {
    const float* x  = (const float*)d_in[0];
    const float* rw = (const float*)d_in[1];
    const float* rb = (const float*)d_in[2];
    const float* w1 = (const float*)d_in[3];
    const float* w2 = (const float*)d_in[4];
    const float* w3 = (const float*)d_in[5];
    float* out = (float*)d_out;

    cudaFuncSetAttribute(gemm1_kernel, cudaFuncAttributeMaxDynamicSharedMemorySize, SMEM1_SZ);
    cudaFuncSetAttribute(gemm2_kernel, cudaFuncAttributeMaxDynamicSharedMemorySize, SMEM2_SZ);

    __half *w1t, *w3t, *w2t;
    float *y1, *y2;
    cudaGetSymbolAddress((void**)&w1t, g_w1t);
    cudaGetSymbolAddress((void**)&w3t, g_w3t);
    cudaGetSymbolAddress((void**)&w2t, g_w2t);
    cudaGetSymbolAddress((void**)&y1, g_Y1);
    cudaGetSymbolAddress((void**)&y2, g_Y2);

    cudaStream_t s1;
    cudaEvent_t e0, e13a, e13b, et2, eg1a;
    cudaStreamCreateWithFlags(&s1, cudaStreamNonBlocking);
    cudaEventCreateWithFlags(&e0,   cudaEventDisableTiming);
    cudaEventCreateWithFlags(&e13a, cudaEventDisableTiming);
    cudaEventCreateWithFlags(&e13b, cudaEventDisableTiming);
    cudaEventCreateWithFlags(&et2,  cudaEventDisableTiming);
    cudaEventCreateWithFlags(&eg1a, cudaEventDisableTiming);

    cudaEventRecord(e0, 0);
    cudaStreamWaitEvent(s1, e0, 0);

    init_kernel<<<1, 32>>>();                                                // #1 main
    transpose13_kernel<<<dim3(64, DDIM / 32, 2 * NEXP), dim3(32, 8), 0, s1>>>(
        w1, w3, w1t, w3t, 0);                                                // #2 s1 (F 0..2047)
    cudaEventRecord(e13a, s1);
    router_fused_kernel<<<256, 256>>>(x, rw, rb);                            // #3 main (+x->fp16)

    cudaStreamWaitEvent(0, e13a, 0);
    gemm1_kernel<<<dim3(MAX_MT, 32), 256, SMEM1_SZ>>>(0);                    // #4 main (profiled)
    cudaEventRecord(eg1a, 0);

    transpose13_kernel<<<dim3(64, DDIM / 32, 2 * NEXP), dim3(32, 8), 0, s1>>>(
        w1, w3, w1t, w3t, 2048);                                             // #5 s1
    cudaEventRecord(e13b, s1);
    transpose2_kernel<<<dim3(DDIM / 32, FDIM / 32, NEXP), dim3(32, 8), 0, s1>>>(
        w2, w2t);                                                            // #6 s1
    cudaEventRecord(et2, s1);

    // gemm2a on s1: consumes H[:, 0:2048]; ordered after t2 on s1, after gemm1a via event
    cudaStreamWaitEvent(s1, eg1a, 0);
    gemm2_kernel<<<dim3(MAX_MT, DDIM / 128), 256, SMEM2_SZ, s1>>>(0, y1);    // #7 s1 (|| gemm1b)

    // gemm1b on main (needs t13b)
    cudaStreamWaitEvent(0, e13b, 0);
    gemm1_kernel<<<dim3(MAX_MT, 32), 256, SMEM1_SZ>>>(2048);                 // #8 main

    // gemm2b on main: needs gemm1b (main order) + t2 (et2) — no false dep on gemm2a
    cudaStreamWaitEvent(0, et2, 0);
    gemm2_kernel<<<dim3(MAX_MT, DDIM / 128), 256, SMEM2_SZ>>>(2048, y2);     // #9 main

    // combine: needs gemm2b (main order) + gemm2a (s1) — join s1
    cudaEvent_t eg2a;
    cudaEventCreateWithFlags(&eg2a, cudaEventDisableTiming);
    cudaEventRecord(eg2a, s1);
    cudaStreamWaitEvent(0, eg2a, 0);
    combine_kernel<<<T_TOKENS, 256>>>(out);                                  // #10 main
}